// round 7
// baseline (speedup 1.0000x reference)
#include <cuda_runtime.h>

#define NF 32
#define NP 496
#define NU (NP + NF)          // 528 units
#define NE 32
#define NH 64
#define FS 64
#define BATCH 2048
#define BT 128                // samples per GEMM tile
#define TILES_PER_BLOCK 4
#define GRID_Y (BATCH / (BT * TILES_PER_BLOCK))   // 4
#define TPAD 66               // padded row length for gather tables (floats)

// ---------------- device scratch ----------------
__device__ float g_T1[NP * FS * NH];
__device__ float g_T2[NP * FS * NH];
__device__ float g_Tm[NF * FS * NH];
__device__ float g_gw2p[NP * NH];
__device__ float g_gw2m[NF * NH];
__device__ float g_C;

__device__ __forceinline__ float smoothz(float z) {
    if (z <= -0.5f) return 0.0f;
    if (z >= 0.5f) return 1.0f;
    return -2.0f * z * z * z + 1.5f * z + 0.5f;
}

__device__ __forceinline__ unsigned long long dupf(float v) {
    unsigned long long r;
    asm("mov.b64 %0, {%1, %1};" : "=l"(r) : "f"(v));
    return r;
}
__device__ __forceinline__ void ffma2(unsigned long long& d,
                                      unsigned long long a,
                                      unsigned long long b) {
    asm("fma.rn.f32x2 %0, %1, %2, %0;" : "+l"(d) : "l"(a), "l"(b));
}
__device__ __forceinline__ float2 unpk(unsigned long long v) {
    float2 u;
    asm("mov.b64 {%0, %1}, %2;" : "=f"(u.x), "=f"(u.y) : "l"(v));
    return u;
}

// ---------------- kernel 1: precompute layer-0 lookup tables ----------------
__global__ __launch_bounds__(256) void precompute_tables(
    const float* __restrict__ emb,
    const int* __restrict__ pairs_list,
    const int* __restrict__ offsets,
    const float* __restrict__ pw0, const float* __restrict__ pb0,
    const float* __restrict__ mw0, const float* __restrict__ mb0)
{
    __shared__ float Es[FS * NE];
    __shared__ float Ws[NE * NH];

    int bid = blockIdx.x;
    int tid = threadIdx.x;

    const float* wsrc;
    const float* bias = nullptr;
    float* dst;
    int embRow0;

    if (bid < NP) {
        int p = bid;
        embRow0 = offsets[pairs_list[2 * p]];
        wsrc = pw0 + (p * 64 + 0) * NH;
        bias = pb0 + p * NH;
        dst = g_T1 + p * FS * NH;
    } else if (bid < 2 * NP) {
        int p = bid - NP;
        embRow0 = offsets[pairs_list[2 * p + 1]];
        wsrc = pw0 + (p * 64 + 32) * NH;
        dst = g_T2 + p * FS * NH;
    } else {
        int f = bid - 2 * NP;
        embRow0 = f * FS;
        wsrc = mw0 + f * NE * NH;
        bias = mb0 + f * NH;
        dst = g_Tm + f * FS * NH;
    }

    for (int i = tid; i < FS * NE; i += 256) Es[i] = emb[embRow0 * NE + i];
    for (int i = tid; i < NE * NH; i += 256) Ws[i] = wsrc[i];
    __syncthreads();

    int v = tid >> 2;
    int j0 = (tid & 3) * 16;
    float acc[16];
#pragma unroll
    for (int t = 0; t < 16; t++) acc[t] = bias ? bias[j0 + t] : 0.0f;
    for (int e = 0; e < NE; e++) {
        float a = Es[v * NE + e];
#pragma unroll
        for (int t = 0; t < 16; t++) acc[t] = fmaf(a, Ws[e * NH + j0 + t], acc[t]);
    }
#pragma unroll
    for (int t = 0; t < 16; t++) dst[v * NH + j0 + t] = acc[t];
}

// ---------------- kernel 2: gated layer-2 weights + bias constant ----------------
__global__ void precompute_gates(
    const float* __restrict__ pw2, const float* __restrict__ pb2, const float* __restrict__ zp,
    const float* __restrict__ mw2, const float* __restrict__ mb2, const float* __restrict__ zm)
{
    int i = blockIdx.x * 256 + threadIdx.x;
    if (i < NP * NH) g_gw2p[i] = pw2[i] * smoothz(zp[i >> 6]);
    if (i < NF * NH) g_gw2m[i] = mw2[i] * smoothz(zm[i >> 6]);
    if (i == 0) {
        float c = 0.0f;
        for (int p = 0; p < NP; p++) c += pb2[p] * smoothz(zp[p]);
        for (int f = 0; f < NF; f++) c += mb2[f] * smoothz(zm[f]);
        g_C = c;
    }
}

// ---------------- kernel 3: init output with constant ----------------
__global__ void init_out(float* __restrict__ out) {
    out[blockIdx.x * 256 + threadIdx.x] = g_C;
}

// ---------------- kernel 4: fused main pass (register-tiled f32x2 GEMM) ----------
// 256 threads. Each tile: 128 samples x 64 cols. Thread tile = 4 rows x 8 cols.
// smem float offsets
#define SM_W1 0
#define SM_T1 4096
#define SM_T2 (SM_T1 + FS * TPAD)      //  8320
#define SM_B1 (SM_T2 + FS * TPAD)      // 12544
#define SM_G2 (SM_B1 + NH)             // 12608
#define SM_H0 (SM_G2 + NH)             // 12672
#define SM_FLOATS (SM_H0 + NH * BT)    // 20864 floats = 83456 B -> 2 CTAs/SM

__global__ __launch_bounds__(256, 2) void fused_pass(
    const int* __restrict__ mains, const int* __restrict__ pairs,
    const float* __restrict__ pw1, const float* __restrict__ mw1,
    const float* __restrict__ pb1, const float* __restrict__ mb1,
    float* __restrict__ out)
{
    extern __shared__ float sm[];
    float* W1s = sm + SM_W1;
    float* T1s = sm + SM_T1;
    float* T2s = sm + SM_T2;
    float* b1s = sm + SM_B1;
    float* g2s = sm + SM_G2;
    float* H0  = sm + SM_H0;           // [NH][BT] transposed, un-duplicated

    int unit = blockIdx.x;
    int tid = threadIdx.x;
    bool isPair = unit < NP;

    const float *t1src, *t2src = nullptr, *w1src, *b1src, *g2src;
    if (isPair) {
        t1src = g_T1 + unit * FS * NH;
        t2src = g_T2 + unit * FS * NH;
        w1src = pw1 + unit * NH * NH;
        b1src = pb1 + unit * NH;
        g2src = g_gw2p + unit * NH;
    } else {
        int f = unit - NP;
        t1src = g_Tm + f * FS * NH;
        w1src = mw1 + f * NH * NH;
        b1src = mb1 + f * NH;
        g2src = g_gw2m + f * NH;
    }

    // ---- stage weights/tables (once per block) ----
    {
        const float2* s1 = (const float2*)t1src;
        for (int i = tid; i < FS * NH / 2; i += 256) {
            int v = i >> 5, j = i & 31;
            *(float2*)&T1s[v * TPAD + 2 * j] = s1[i];
        }
        if (isPair) {
            const float2* s2 = (const float2*)t2src;
            for (int i = tid; i < FS * NH / 2; i += 256) {
                int v = i >> 5, j = i & 31;
                *(float2*)&T2s[v * TPAD + 2 * j] = s2[i];
            }
        }
        const float4* sw = (const float4*)w1src;
        for (int i = tid; i < NH * NH / 4; i += 256) ((float4*)W1s)[i] = sw[i];
        if (tid < NH) { b1s[tid] = b1src[tid]; g2s[tid] = g2src[tid]; }
    }
    __syncthreads();

    int tr = tid >> 3;        // 0..31  (row group: 4 rows each)
    int tc = tid & 7;         // 0..7   (col group: 8 cols each)
    int h  = tid >> 7;        // 0/1    (gather: which half of the 64 h0 values)
    int s  = tid & 127;       // gather: sample within tile

    for (int t = 0; t < TILES_PER_BLOCK; t++) {
        int base = (blockIdx.y * TILES_PER_BLOCK + t) * BT;

        // ---- layer 0 gather -> H0 transposed (2 threads per sample) ----
        // float2 loads only: T rows are 8B-aligned (TPAD*4 = 264 ≡ 0 mod 8).
        {
            int b = base + s;
            int jbase = h * 32;
            if (isPair) {
                int2 ii = ((const int2*)pairs)[b * NP + unit];
                const float* r1 = &T1s[ii.x * TPAD + jbase];
                const float* r2 = &T2s[ii.y * TPAD + jbase];
#pragma unroll
                for (int j = 0; j < 32; j += 2) {
                    float2 a = *(const float2*)&r1[j];
                    float2 c = *(const float2*)&r2[j];
                    H0[(jbase + j + 0) * BT + s] = fmaxf(a.x + c.x, 0.0f);
                    H0[(jbase + j + 1) * BT + s] = fmaxf(a.y + c.y, 0.0f);
                }
            } else {
                int i1 = mains[b * NF + (unit - NP)];
                const float* r1 = &T1s[i1 * TPAD + jbase];
#pragma unroll
                for (int j = 0; j < 32; j += 2) {
                    float2 a = *(const float2*)&r1[j];
                    H0[(jbase + j + 0) * BT + s] = fmaxf(a.x, 0.0f);
                    H0[(jbase + j + 1) * BT + s] = fmaxf(a.y, 0.0f);
                }
            }
        }
        __syncthreads();

        // ---- GEMM: C[128x64] = H0^T[128x64] @ W1[64x64], 4x8 thread tile ----
        unsigned long long acc[4][4];
#pragma unroll
        for (int i = 0; i < 4; i++)
#pragma unroll
            for (int j = 0; j < 4; j++) acc[i][j] = 0ull;

        const float* ap = H0 + (tr << 2);
        const float* wp0 = W1s + (tc << 3);
#pragma unroll 4
        for (int k = 0; k < NH; k++) {
            float4 a4 = *(const float4*)(ap + k * BT);
            unsigned long long av[4] = {dupf(a4.x), dupf(a4.y), dupf(a4.z), dupf(a4.w)};
            const ulonglong2* wp = (const ulonglong2*)(wp0 + k * NH);
            ulonglong2 b01 = wp[0];
            ulonglong2 b23 = wp[1];
            unsigned long long bv[4] = {b01.x, b01.y, b23.x, b23.y};
#pragma unroll
            for (int i = 0; i < 4; i++) {
#pragma unroll
                for (int j = 0; j < 4; j++) ffma2(acc[i][j], av[i], bv[j]);
            }
        }

        // ---- epilogue: +b1, relu, dot g2, reduce over col groups, atomicAdd ----
        float part[4];
#pragma unroll
        for (int i = 0; i < 4; i++) part[i] = 0.0f;
#pragma unroll
        for (int j = 0; j < 4; j++) {
            float2 bb = ((const float2*)&b1s[tc * 8])[j];
            float2 gg = ((const float2*)&g2s[tc * 8])[j];
#pragma unroll
            for (int i = 0; i < 4; i++) {
                float2 c = unpk(acc[i][j]);
                part[i] = fmaf(fmaxf(c.x + bb.x, 0.0f), gg.x, part[i]);
                part[i] = fmaf(fmaxf(c.y + bb.y, 0.0f), gg.y, part[i]);
            }
        }
#pragma unroll
        for (int off = 1; off < 8; off <<= 1) {
#pragma unroll
            for (int i = 0; i < 4; i++)
                part[i] += __shfl_xor_sync(0xffffffffu, part[i], off);
        }
        if (tc == 0) {
#pragma unroll
            for (int i = 0; i < 4; i++)
                atomicAdd(&out[base + (tr << 2) + i], part[i]);
        }
        __syncthreads();   // protect H0 reuse by next tile
    }
}

// ---------------- launch ----------------
extern "C" void kernel_launch(void* const* d_in, const int* in_sizes, int n_in,
                              void* d_out, int out_size)
{
    const int*   mains      = (const int*)d_in[0];
    const int*   pairs      = (const int*)d_in[1];
    const int*   pairs_list = (const int*)d_in[2];
    const int*   offsets    = (const int*)d_in[3];
    const float* embedding  = (const float*)d_in[4];
    const float* mw0        = (const float*)d_in[5];
    const float* mw1        = (const float*)d_in[6];
    const float* mw2        = (const float*)d_in[7];
    const float* mb0        = (const float*)d_in[8];
    const float* mb1        = (const float*)d_in[9];
    const float* mb2        = (const float*)d_in[10];
    const float* pw0        = (const float*)d_in[11];
    const float* pw1        = (const float*)d_in[12];
    const float* pw2        = (const float*)d_in[13];
    const float* pb0        = (const float*)d_in[14];
    const float* pb1        = (const float*)d_in[15];
    const float* pb2        = (const float*)d_in[16];
    const float* z_main     = (const float*)d_in[17];
    const float* z_pairs    = (const float*)d_in[18];
    float* out = (float*)d_out;

    static int attr_set = 0;
    const int smem_bytes = SM_FLOATS * (int)sizeof(float);
    if (!attr_set) {
        cudaFuncSetAttribute(fused_pass, cudaFuncAttributeMaxDynamicSharedMemorySize, smem_bytes);
        attr_set = 1;
    }

    precompute_tables<<<2 * NP + NF, 256>>>(embedding, pairs_list, offsets,
                                            pw0, pb0, mw0, mb0);
    precompute_gates<<<(NP * NH + 255) / 256, 256>>>(pw2, pb2, z_pairs, mw2, mb2, z_main);
    init_out<<<BATCH / 256, 256>>>(out);

    dim3 grid(NU, GRID_Y);
    fused_pass<<<grid, 256, smem_bytes>>>(mains, pairs, pw1, mw1, pb1, mb1, out);
}

// round 10
// speedup vs baseline: 1.2095x; 1.2095x over previous
#include <cuda_runtime.h>
#include <cstdint>

#define NF 32
#define NP 496
#define NU 528
#define NE 32
#define NH 64
#define FS 64
#define BATCH 2048
#define BT 256                // samples per GEMM tile
#define TILES_PER_BLOCK 2
#define GRID_Y 4              // 4 * 2 * 256 = 2048

// ---------------- device scratch ----------------
__device__ __align__(128) float g_T1[NP * FS * NH];
__device__ __align__(128) float g_T2[NP * FS * NH];
__device__ __align__(128) float g_Tm[NF * FS * NH];
__device__ float g_gw2p[NP * NH];
__device__ float g_gw2m[NF * NH];
__device__ float g_C;

__device__ __forceinline__ float smoothz(float z) {
    if (z <= -0.5f) return 0.0f;
    if (z >= 0.5f) return 1.0f;
    return -2.0f * z * z * z + 1.5f * z + 0.5f;
}

__device__ __forceinline__ unsigned long long dupf(float v) {
    unsigned long long r;
    asm("mov.b64 %0, {%1, %1};" : "=l"(r) : "f"(v));
    return r;
}
__device__ __forceinline__ void ffma2(unsigned long long& d,
                                      unsigned long long a,
                                      unsigned long long b) {
    asm("fma.rn.f32x2 %0, %1, %2, %0;" : "+l"(d) : "l"(a), "l"(b));
}
__device__ __forceinline__ float2 unpk(unsigned long long v) {
    float2 u;
    asm("mov.b64 {%0, %1}, %2;" : "=f"(u.x), "=f"(u.y) : "l"(v));
    return u;
}

// ---------------- kernel 1: precompute layer-0 lookup tables ----------------
__global__ __launch_bounds__(256) void precompute_tables(
    const float* __restrict__ emb,
    const int* __restrict__ pairs_list,
    const int* __restrict__ offsets,
    const float* __restrict__ pw0, const float* __restrict__ pb0,
    const float* __restrict__ mw0, const float* __restrict__ mb0)
{
    __shared__ float Es[FS * NE];
    __shared__ float Ws[NE * NH];

    int bid = blockIdx.x;
    int tid = threadIdx.x;

    const float* wsrc;
    const float* bias = nullptr;
    float* dst;
    int embRow0;

    if (bid < NP) {
        int p = bid;
        embRow0 = offsets[pairs_list[2 * p]];
        wsrc = pw0 + (p * 64 + 0) * NH;
        bias = pb0 + p * NH;
        dst = g_T1 + p * FS * NH;
    } else if (bid < 2 * NP) {
        int p = bid - NP;
        embRow0 = offsets[pairs_list[2 * p + 1]];
        wsrc = pw0 + (p * 64 + 32) * NH;
        dst = g_T2 + p * FS * NH;
    } else {
        int f = bid - 2 * NP;
        embRow0 = f * FS;
        wsrc = mw0 + f * NE * NH;
        bias = mb0 + f * NH;
        dst = g_Tm + f * FS * NH;
    }

    for (int i = tid; i < FS * NE; i += 256) Es[i] = emb[embRow0 * NE + i];
    for (int i = tid; i < NE * NH; i += 256) Ws[i] = wsrc[i];
    __syncthreads();

    int v = tid >> 2;
    int j0 = (tid & 3) * 16;
    float acc[16];
#pragma unroll
    for (int t = 0; t < 16; t++) acc[t] = bias ? bias[j0 + t] : 0.0f;
    for (int e = 0; e < NE; e++) {
        float a = Es[v * NE + e];
#pragma unroll
        for (int t = 0; t < 16; t++) acc[t] = fmaf(a, Ws[e * NH + j0 + t], acc[t]);
    }
#pragma unroll
    for (int t = 0; t < 16; t++) dst[v * NH + j0 + t] = acc[t];
}

// ---------------- kernel 2: gated layer-2 weights + bias constant ----------------
__global__ void precompute_gates(
    const float* __restrict__ pw2, const float* __restrict__ pb2, const float* __restrict__ zp,
    const float* __restrict__ mw2, const float* __restrict__ mb2, const float* __restrict__ zm)
{
    int i = blockIdx.x * 256 + threadIdx.x;
    if (i < NP * NH) g_gw2p[i] = pw2[i] * smoothz(zp[i >> 6]);
    if (i < NF * NH) g_gw2m[i] = mw2[i] * smoothz(zm[i >> 6]);
    if (i == 0) {
        float c = 0.0f;
        for (int p = 0; p < NP; p++) c += pb2[p] * smoothz(zp[p]);
        for (int f = 0; f < NF; f++) c += mb2[f] * smoothz(zm[f]);
        g_C = c;
    }
}

// ---------------- kernel 3: init output with constant ----------------
__global__ void init_out(float* __restrict__ out) {
    out[blockIdx.x * 256 + threadIdx.x] = g_C;
}

// ---------------- kernel 4: fused main pass -------------------------------------
// 256 threads, 2 CTAs/SM. Tile = 256 samples x 64 cols, thread tile 8x8 (f32x2).
// W stored in two conflict-free planes:
//   WA[k][c][0..3] = W1[k][8c .. 8c+3], WB[k][c][0..3] = W1[k][8c+4 .. 8c+7]
// (rows of 128B -> 8 distinct 16B chunks per warp-phase -> no bank conflicts)
// H0[64][256] transposed fp32. Gather reads tables straight from global (L2).
#define SM_WA 0
#define SM_WB (SM_WA + NH * 32)          //  2048 floats
#define SM_B1 (SM_WB + NH * 32)          //  4096
#define SM_G2 (SM_B1 + NH)               //  4160
#define SM_H0 (SM_G2 + NH)               //  4224
#define SM_FLOATS (SM_H0 + NH * BT)      // 20608 floats = 82432 B -> 2 CTAs/SM

__global__ __launch_bounds__(256, 2) void fused_pass(
    const int* __restrict__ mains, const int* __restrict__ pairs,
    const float* __restrict__ pw1, const float* __restrict__ mw1,
    const float* __restrict__ pb1, const float* __restrict__ mb1,
    float* __restrict__ out)
{
    extern __shared__ float sm[];
    float* WAs = sm + SM_WA;
    float* WBs = sm + SM_WB;
    float* b1s = sm + SM_B1;
    float* g2s = sm + SM_G2;
    float* H0  = sm + SM_H0;

    int unit = blockIdx.x;
    int tid = threadIdx.x;
    bool isPair = unit < NP;

    const float *t1src, *t2src = nullptr, *w1src, *b1src, *g2src;
    if (isPair) {
        t1src = g_T1 + unit * FS * NH;
        t2src = g_T2 + unit * FS * NH;
        w1src = pw1 + unit * NH * NH;
        b1src = pb1 + unit * NH;
        g2src = g_gw2p + unit * NH;
    } else {
        int f = unit - NP;
        t1src = g_Tm + f * FS * NH;
        w1src = mw1 + f * NH * NH;
        b1src = mb1 + f * NH;
        g2src = g_gw2m + f * NH;
    }

    // ---- stage W into split planes (once per block) ----
    {
        const float4* sw = (const float4*)w1src;
#pragma unroll
        for (int it = 0; it < 4; it++) {
            int i = it * 256 + tid;              // i in [0,1024): one float4 of W
            float4 v = sw[i];
            int k = i >> 4;
            int rem = i & 15;
            int c = rem >> 1;
            float* dst = (rem & 1) ? WBs : WAs;
            *(float4*)&dst[k * 32 + c * 4] = v;
        }
        if (tid < NH) { b1s[tid] = b1src[tid]; g2s[tid] = g2src[tid]; }
    }

    int tr = tid >> 3;        // 0..31 (8 rows each)
    int tc = tid & 7;         // 0..7  (8 cols each)

    for (int t = 0; t < TILES_PER_BLOCK; t++) {
        int base = (blockIdx.y * TILES_PER_BLOCK + t) * BT;
        int b = base + tid;

        if (t > 0) __syncthreads();   // H0 from previous tile fully consumed
        else __syncthreads();         // W planes visible

        // ---- gather from GLOBAL tables (L2-resident) -> H0 transposed ----
        if (isPair) {
            int2 ii = ((const int2*)pairs)[b * NP + unit];
            const float4* r1 = (const float4*)(t1src + ii.x * NH);
            const float4* r2 = (const float4*)(t2src + ii.y * NH);
#pragma unroll
            for (int q = 0; q < 16; q++) {
                float4 a = r1[q];
                float4 c = r2[q];
                H0[(4 * q + 0) * BT + tid] = fmaxf(a.x + c.x, 0.0f);
                H0[(4 * q + 1) * BT + tid] = fmaxf(a.y + c.y, 0.0f);
                H0[(4 * q + 2) * BT + tid] = fmaxf(a.z + c.z, 0.0f);
                H0[(4 * q + 3) * BT + tid] = fmaxf(a.w + c.w, 0.0f);
            }
        } else {
            int i1 = mains[b * NF + (unit - NP)];
            const float4* r1 = (const float4*)(t1src + i1 * NH);
#pragma unroll
            for (int q = 0; q < 16; q++) {
                float4 a = r1[q];
                H0[(4 * q + 0) * BT + tid] = fmaxf(a.x, 0.0f);
                H0[(4 * q + 1) * BT + tid] = fmaxf(a.y, 0.0f);
                H0[(4 * q + 2) * BT + tid] = fmaxf(a.z, 0.0f);
                H0[(4 * q + 3) * BT + tid] = fmaxf(a.w, 0.0f);
            }
        }
        __syncthreads();

        // ---- GEMM: C[256x64] = H0^T @ W1, 8x8 thread tile, f32x2 ----
        unsigned long long acc[8][4];
#pragma unroll
        for (int i = 0; i < 8; i++)
#pragma unroll
            for (int j = 0; j < 4; j++) acc[i][j] = 0ull;

        const float* ap = H0 + (tr << 3);
        const float* wa = WAs + (tc << 2);
        const float* wb = WBs + (tc << 2);
#pragma unroll 4
        for (int k = 0; k < NH; k++) {
            float4 a0 = *(const float4*)(ap + k * BT);
            float4 a1 = *(const float4*)(ap + k * BT + 4);
            unsigned long long av[8] = {dupf(a0.x), dupf(a0.y), dupf(a0.z), dupf(a0.w),
                                        dupf(a1.x), dupf(a1.y), dupf(a1.z), dupf(a1.w)};
            ulonglong2 bA = *(const ulonglong2*)(wa + k * 32);
            ulonglong2 bB = *(const ulonglong2*)(wb + k * 32);
            unsigned long long bv[4] = {bA.x, bA.y, bB.x, bB.y};
#pragma unroll
            for (int i = 0; i < 8; i++) {
#pragma unroll
                for (int j = 0; j < 4; j++) ffma2(acc[i][j], av[i], bv[j]);
            }
        }

        // ---- epilogue: +b1, relu, dot g2 ----
        // acc[i][0..1] -> cols 8tc+0..3 (WA plane), acc[i][2..3] -> cols 8tc+4..7 (WB)
        float part[8];
#pragma unroll
        for (int i = 0; i < 8; i++) part[i] = 0.0f;
#pragma unroll
        for (int j = 0; j < 4; j++) {
            int col = tc * 8 + ((j < 2) ? 2 * j : 2 * j);   // 0,2 then 4,6 offsets
            float2 bb = *(const float2*)&b1s[tc * 8 + 2 * j];
            float2 gg = *(const float2*)&g2s[tc * 8 + 2 * j];
            (void)col;
#pragma unroll
            for (int i = 0; i < 8; i++) {
                float2 c = unpk(acc[i][j]);
                part[i] = fmaf(fmaxf(c.x + bb.x, 0.0f), gg.x, part[i]);
                part[i] = fmaf(fmaxf(c.y + bb.y, 0.0f), gg.y, part[i]);
            }
        }
#pragma unroll
        for (int off = 1; off < 8; off <<= 1) {
#pragma unroll
            for (int i = 0; i < 8; i++)
                part[i] += __shfl_xor_sync(0xffffffffu, part[i], off);
        }
        if (tc == 0) {
#pragma unroll
            for (int i = 0; i < 8; i++)
                atomicAdd(&out[base + (tr << 3) + i], part[i]);
        }
    }
}

// ---------------- launch ----------------
extern "C" void kernel_launch(void* const* d_in, const int* in_sizes, int n_in,
                              void* d_out, int out_size)
{
    const int*   mains      = (const int*)d_in[0];
    const int*   pairs      = (const int*)d_in[1];
    const int*   pairs_list = (const int*)d_in[2];
    const int*   offsets    = (const int*)d_in[3];
    const float* embedding  = (const float*)d_in[4];
    const float* mw0        = (const float*)d_in[5];
    const float* mw1        = (const float*)d_in[6];
    const float* mw2        = (const float*)d_in[7];
    const float* mb0        = (const float*)d_in[8];
    const float* mb1        = (const float*)d_in[9];
    const float* mb2        = (const float*)d_in[10];
    const float* pw0        = (const float*)d_in[11];
    const float* pw1        = (const float*)d_in[12];
    const float* pw2        = (const float*)d_in[13];
    const float* pb0        = (const float*)d_in[14];
    const float* pb1        = (const float*)d_in[15];
    const float* pb2        = (const float*)d_in[16];
    const float* z_main     = (const float*)d_in[17];
    const float* z_pairs    = (const float*)d_in[18];
    float* out = (float*)d_out;

    static int attr_set = 0;
    const int smem_bytes = SM_FLOATS * (int)sizeof(float);
    if (!attr_set) {
        cudaFuncSetAttribute(fused_pass, cudaFuncAttributeMaxDynamicSharedMemorySize, smem_bytes);
        attr_set = 1;
    }

    precompute_tables<<<2 * NP + NF, 256>>>(embedding, pairs_list, offsets,
                                            pw0, pb0, mw0, mb0);
    precompute_gates<<<(NP * NH + 255) / 256, 256>>>(pw2, pb2, z_pairs, mw2, mb2, z_main);
    init_out<<<BATCH / 256, 256>>>(out);

    dim3 grid(NU, GRID_Y);
    fused_pass<<<grid, 256, smem_bytes>>>(mains, pairs, pw1, mw1, pb1, mb1, out);
}